// round 13
// baseline (speedup 1.0000x reference)
#include <cuda_runtime.h>
#include <cuda_fp16.h>
#include <cstdint>

// ---------------------------------------------------------------------------
// GCN via TF32 tensor-core GEMMs + CSR warp aggregation.
//   hs = (x@W) * dinv[row]  stored FP16 (same 10-bit mantissa as tf32)
//   out[d] = relu( (hs[d] + sum_{e->d} hs[src]) * dinv[d] + b )  fp32 accum
// CSR build: rank-based atomic-free scatter, fused small launches.
// ---------------------------------------------------------------------------

#define N_MAX 100000
#define E_MAX 1600000
#define F_IN  128
#define F_HID 64
#define F_OUT 32

__device__ int   g_is64;
__device__ int   g_deg[N_MAX];
__device__ float g_dinv[N_MAX];
__device__ int   g_rowstart[N_MAX + 1];
__device__ int   g_rank[E_MAX];
__device__ int   g_colsrc[E_MAX];
__device__ int   g_blocksums[128];
__device__ float g_bufA[N_MAX * F_HID];   // holds fp16 h (half the bytes used)
__device__ float g_bufB[N_MAX * F_HID];   // fp32 z

__device__ __forceinline__ const float* pick_src(int sel, const float* ext) {
    if (sel == 1) return g_bufA;
    if (sel == 2) return g_bufB;
    return ext;
}
__device__ __forceinline__ float* pick_dst(int sel, float* ext) {
    if (sel == 1) return g_bufA;
    if (sel == 2) return g_bufB;
    return ext;
}

__device__ __forceinline__ uint32_t f2tf32(float f) {
    uint32_t u;
    asm("cvt.rna.tf32.f32 %0, %1;" : "=r"(u) : "f"(f));
    return u;
}

__device__ __forceinline__ void mma_tf32(float* c, const uint32_t* a,
                                         uint32_t b0, uint32_t b1) {
    asm volatile(
        "mma.sync.aligned.m16n8k8.row.col.f32.tf32.tf32.f32 "
        "{%0,%1,%2,%3}, {%4,%5,%6,%7}, {%8,%9}, {%0,%1,%2,%3};"
        : "+f"(c[0]), "+f"(c[1]), "+f"(c[2]), "+f"(c[3])
        : "r"(a[0]), "r"(a[1]), "r"(a[2]), "r"(a[3]), "r"(b0), "r"(b1));
}

// ---------------- detect + init degree (fused) -----------------------------

__global__ void init_detect_kernel(const int* __restrict__ ew, int n) {
    int i = blockIdx.x * blockDim.x + threadIdx.x;
    if (i < n) g_deg[i] = 1;  // self loop
    if (blockIdx.x == 0 && threadIdx.x == 0) {
        int is64 = 1;
        for (int j = 0; j < 32; ++j)
            if (ew[2 * j + 1] != 0) { is64 = 0; break; }
        g_is64 = is64;
    }
}

// ---------------- degree histogram (returns rank) --------------------------

__global__ void deg_hist_kernel(const int* __restrict__ ew, int E) {
    int i = blockIdx.x * blockDim.x + threadIdx.x;
    if (i < E) {
        int d = g_is64 ? ew[2 * E + 2 * i] : ew[E + i];
        g_rank[i] = atomicAdd(&g_deg[d], 1);   // old value = rank (>=1)
    }
}

// ---------------- scan (CSR offsets) ---------------------------------------

__global__ void scan_block_kernel(int n) {
    __shared__ int wsum[32];
    int t = threadIdx.x, lane = t & 31, wid = t >> 5;
    int gid = blockIdx.x * 1024 + t;
    int v = (gid < n) ? (g_deg[gid] - 1) : 0;  // counts exclude self loop
    int s = v;
#pragma unroll
    for (int off = 1; off < 32; off <<= 1) {
        int u = __shfl_up_sync(0xffffffffu, s, off);
        if (lane >= off) s += u;
    }
    if (lane == 31) wsum[wid] = s;
    __syncthreads();
    if (wid == 0) {
        int wv = wsum[lane];
        int ss = wv;
#pragma unroll
        for (int off = 1; off < 32; off <<= 1) {
            int u = __shfl_up_sync(0xffffffffu, ss, off);
            if (lane >= off) ss += u;
        }
        wsum[lane] = ss - wv;                  // exclusive warp offsets
        if (lane == 31) g_blocksums[blockIdx.x] = ss;  // block totals
    }
    __syncthreads();
    if (gid < n) g_rowstart[gid] = s - v + wsum[wid];  // exclusive in block
}

// fold the block-sums scan in (each block rescans 128 sums); also dinv
__global__ void scan_fix_kernel(int n, int E, int nb) {
    __shared__ int pref[128];
    int t = threadIdx.x;
    if (t < 128) pref[t] = (t < nb) ? g_blocksums[t] : 0;
    __syncthreads();
#pragma unroll
    for (int off = 1; off < 128; off <<= 1) {
        int add = (t < 128 && t >= off) ? pref[t - off] : 0;
        __syncthreads();
        if (t < 128) pref[t] += add;
        __syncthreads();
    }
    int gid = blockIdx.x * 256 + t;
    if (gid < n) {
        int b = gid >> 10;
        int base = (b == 0) ? 0 : pref[b - 1];
        g_rowstart[gid] += base;
        g_dinv[gid] = rsqrtf((float)g_deg[gid]);
    }
    if (gid == 0) g_rowstart[n] = E;
}

// atomic-free scatter using saved rank
__global__ void scatter_kernel(const int* __restrict__ ew, int E) {
    int i = blockIdx.x * blockDim.x + threadIdx.x;
    if (i < E) {
        int d, s;
        if (g_is64) {
            s = ew[2 * i];
            d = ew[2 * E + 2 * i];
        } else {
            s = ew[i];
            d = ew[E + i];
        }
        g_colsrc[g_rowstart[d] + g_rank[i] - 1] = s;
    }
}

// ------------------------------ TF32 MMA GEMM ------------------------------
// C[M,NOUT] = A[M,K] @ W[K,NOUT]; row-scale by dinv (DINV) and/or +bias.
// HOUT: write results as fp16 (half2) instead of fp32.

template <int K, int NOUT, bool DINV, bool BIAS, bool HOUT>
__global__ __launch_bounds__(256) void mma_gemm_kernel(
    const float* __restrict__ Aext, int asel,
    const float* __restrict__ W, const float* __restrict__ bias,
    float* __restrict__ Cext, int csel, int M) {
    const float* A = pick_src(asel, Aext);
    float*       C = pick_dst(csel, Cext);
    __half2*     Ch = (__half2*)C;

    constexpr int KC = 32;
    constexpr int AS = KC + 4;           // bank = (4g+tig)%32 : distinct
    constexpr int WS = NOUT + 8;         // bank = (8tig+g)%32 : distinct
    constexpr int WARP_N = NOUT / 2;     // 32 or 16
    constexpr int NF = WARP_N / 8;       // 4 or 2
    __shared__ float xs[128][AS];        // tf32 bits
    __shared__ float ws[KC][WS];         // tf32 bits

    int t    = threadIdx.x;
    int wid  = t >> 5, lane = t & 31;
    int wm   = wid >> 1;                 // 0..3 -> rows wm*32
    int wn   = wid & 1;                  // cols wn*WARP_N
    int g    = lane >> 2, tig = lane & 3;
    int row0 = blockIdx.x * 128;

    float c[2][NF][4];
#pragma unroll
    for (int mf = 0; mf < 2; ++mf)
#pragma unroll
        for (int nf = 0; nf < NF; ++nf)
#pragma unroll
            for (int j = 0; j < 4; ++j) c[mf][nf][j] = 0.f;

    for (int kc = 0; kc < K; kc += KC) {
        // stage A (tf32): 128 x 32, 4 float4 per thread, conflict-free STS.128
#pragma unroll
        for (int i = 0; i < 4; ++i) {
            int f4 = t + i * 256;
            int r  = f4 >> 3;
            int k4 = (f4 & 7) * 4;
            float4 v = make_float4(0.f, 0.f, 0.f, 0.f);
            int gr = row0 + r;
            if (gr < M) v = *(const float4*)&A[(size_t)gr * K + kc + k4];
            float4 tv;
            tv.x = __uint_as_float(f2tf32(v.x));
            tv.y = __uint_as_float(f2tf32(v.y));
            tv.z = __uint_as_float(f2tf32(v.z));
            tv.w = __uint_as_float(f2tf32(v.w));
            *(float4*)&xs[r][k4] = tv;
        }
        // stage W (tf32): 32 x NOUT
#pragma unroll
        for (int i = 0; i < (KC * NOUT) / 1024; ++i) {
            int f4 = t + i * 256;
            int k  = f4 / (NOUT / 4);
            int c4 = (f4 % (NOUT / 4)) * 4;
            float4 v = *(const float4*)&W[(kc + k) * NOUT + c4];
            float4 tv;
            tv.x = __uint_as_float(f2tf32(v.x));
            tv.y = __uint_as_float(f2tf32(v.y));
            tv.z = __uint_as_float(f2tf32(v.z));
            tv.w = __uint_as_float(f2tf32(v.w));
            *(float4*)&ws[k][c4] = tv;
        }
        __syncthreads();
#pragma unroll
        for (int ks = 0; ks < KC / 8; ++ks) {
            int k0 = ks * 8;
            uint32_t a[2][4];
#pragma unroll
            for (int mf = 0; mf < 2; ++mf) {
                int rb = wm * 32 + mf * 16 + g;
                a[mf][0] = __float_as_uint(xs[rb][k0 + tig]);
                a[mf][1] = __float_as_uint(xs[rb + 8][k0 + tig]);
                a[mf][2] = __float_as_uint(xs[rb][k0 + tig + 4]);
                a[mf][3] = __float_as_uint(xs[rb + 8][k0 + tig + 4]);
            }
#pragma unroll
            for (int nf = 0; nf < NF; ++nf) {
                int nb = wn * WARP_N + nf * 8 + g;
                uint32_t b0 = __float_as_uint(ws[k0 + tig][nb]);
                uint32_t b1 = __float_as_uint(ws[k0 + tig + 4][nb]);
                mma_tf32(c[0][nf], a[0], b0, b1);
                mma_tf32(c[1][nf], a[1], b0, b1);
            }
        }
        __syncthreads();
    }

    // epilogue
#pragma unroll
    for (int mf = 0; mf < 2; ++mf) {
        int rA = row0 + wm * 32 + mf * 16 + g;
        int rB = rA + 8;
        float sA = 1.f, sB = 1.f;
        if (DINV) {
            if (rA < M) sA = g_dinv[rA];
            if (rB < M) sB = g_dinv[rB];
        }
#pragma unroll
        for (int nf = 0; nf < NF; ++nf) {
            int cb = wn * WARP_N + nf * 8 + tig * 2;
            float b0 = 0.f, b1 = 0.f;
            if (BIAS) { b0 = bias[cb]; b1 = bias[cb + 1]; }
            if (HOUT) {
                if (rA < M)
                    Ch[((size_t)rA * NOUT + cb) >> 1] = __floats2half2_rn(
                        c[mf][nf][0] * sA + b0, c[mf][nf][1] * sA + b1);
                if (rB < M)
                    Ch[((size_t)rB * NOUT + cb) >> 1] = __floats2half2_rn(
                        c[mf][nf][2] * sB + b0, c[mf][nf][3] * sB + b1);
            } else {
                if (rA < M)
                    *(float2*)&C[(size_t)rA * NOUT + cb] = make_float2(
                        c[mf][nf][0] * sA + b0, c[mf][nf][1] * sA + b1);
                if (rB < M)
                    *(float2*)&C[(size_t)rB * NOUT + cb] = make_float2(
                        c[mf][nf][2] * sB + b0, c[mf][nf][3] * sB + b1);
            }
        }
    }
}

// ------------------------------ aggregation --------------------------------
// hs stored fp16 (dinv-scaled). One warp per dst node; fp32 accumulators.
// out[d] = relu( (hs[d] + sum_e hs[src_e]) * dinv[d] + b )   -> fp32

__global__ __launch_bounds__(256) void aggregate_kernel(
    int hsel, const float* __restrict__ bias, int osel, int n) {
    const __half2* h  = (const __half2*)pick_src(hsel, nullptr);
    float2*       out = (float2*)pick_dst(osel, nullptr);

    int gw   = (blockIdx.x * blockDim.x + threadIdx.x) >> 5;
    int lane = threadIdx.x & 31;
    if (gw >= n) return;
    int d = gw;
    float di = g_dinv[d];
    float2 hv = __half22float2(h[(size_t)d * 32 + lane]);
    float ax = hv.x, ay = hv.y;          // self term (hs[d])

    int e0 = g_rowstart[d], e1 = g_rowstart[d + 1];
    int e  = e0;
    for (; e + 4 <= e1; e += 4) {
        int s0 = g_colsrc[e + 0];
        int s1 = g_colsrc[e + 1];
        int s2 = g_colsrc[e + 2];
        int s3 = g_colsrc[e + 3];
        float2 v0 = __half22float2(h[(size_t)s0 * 32 + lane]);
        float2 v1 = __half22float2(h[(size_t)s1 * 32 + lane]);
        float2 v2 = __half22float2(h[(size_t)s2 * 32 + lane]);
        float2 v3 = __half22float2(h[(size_t)s3 * 32 + lane]);
        ax += v0.x; ay += v0.y;
        ax += v1.x; ay += v1.y;
        ax += v2.x; ay += v2.y;
        ax += v3.x; ay += v3.y;
    }
    for (; e < e1; ++e) {
        int s = g_colsrc[e];
        float2 v = __half22float2(h[(size_t)s * 32 + lane]);
        ax += v.x; ay += v.y;
    }

    ax = fmaf(ax, di, bias[2 * lane]);
    ay = fmaf(ay, di, bias[2 * lane + 1]);
    ax = fmaxf(ax, 0.f);
    ay = fmaxf(ay, 0.f);
    out[(size_t)d * 32 + lane] = make_float2(ax, ay);
}

// ------------------------------ launch -------------------------------------

extern "C" void kernel_launch(void* const* d_in, const int* in_sizes, int n_in,
                              void* d_out, int out_size) {
    const float* x   = (const float*)d_in[0];
    const int*   ew  = (const int*)d_in[1];    // edge words (int32 view)
    const float* W1  = (const float*)d_in[3];
    const float* b1  = (const float*)d_in[4];
    const float* W2  = (const float*)d_in[5];
    const float* b2  = (const float*)d_in[6];
    const float* Wfc = (const float*)d_in[7];
    const float* bfc = (const float*)d_in[8];
    float*       out = (float*)d_out;

    int n = in_sizes[0] / F_IN;
    int E = in_sizes[1] / 2;

    int nb  = (n + 1023) / 1024;
    int gbN = (n + 255) / 256;
    int gbE = (E + 255) / 256;

    init_detect_kernel<<<gbN, 256>>>(ew, n);
    deg_hist_kernel<<<gbE, 256>>>(ew, E);
    scan_block_kernel<<<nb, 1024>>>(n);
    scan_fix_kernel<<<gbN, 256>>>(n, E, nb);
    scatter_kernel<<<gbE, 256>>>(ew, E);

    int gbG  = (n + 127) / 128;
    int gbAg = (n * 32 + 255) / 256;

    // layer 1: bufA = fp16((x@W1)*dinv) ; bufB = relu(agg*dinv + b1) fp32
    mma_gemm_kernel<F_IN, F_HID, true, false, true><<<gbG, 256>>>(
        x, 0, W1, nullptr, nullptr, 1, n);
    aggregate_kernel<<<gbAg, 256>>>(1, b1, 2, n);
    // layer 2
    mma_gemm_kernel<F_HID, F_HID, true, false, true><<<gbG, 256>>>(
        nullptr, 2, W2, nullptr, nullptr, 1, n);
    aggregate_kernel<<<gbAg, 256>>>(1, b2, 2, n);
    // FC: out = bufB@Wfc + bfc   (fp32 out)
    mma_gemm_kernel<F_HID, F_OUT, false, true, false><<<gbG, 256>>>(
        nullptr, 2, Wfc, bfc, out, 0, n);
}

// round 15
// speedup vs baseline: 1.0523x; 1.0523x over previous
#include <cuda_runtime.h>
#include <cuda_fp16.h>
#include <cstdint>

// ---------------------------------------------------------------------------
// GCN via TF32 tensor-core GEMMs + CSR warp aggregation.
//   hs = (x@W) * dinv[row]  (fp32; fp16 measured neutral-to-worse in R13)
//   out[d] = relu( (hs[d] + sum_{e->d} hs[src]) * dinv[d] + b )
// Aggregate inner loop: 8-deep gather pipeline (latency-bound, not BW-bound).
// ---------------------------------------------------------------------------

#define N_MAX 100000
#define E_MAX 1600000
#define F_IN  128
#define F_HID 64
#define F_OUT 32

__device__ int   g_is64;
__device__ int   g_deg[N_MAX];
__device__ float g_dinv[N_MAX];
__device__ int   g_rowstart[N_MAX + 1];
__device__ int   g_rank[E_MAX];
__device__ int   g_colsrc[E_MAX];
__device__ int   g_blocksums[128];
__device__ float g_bufA[N_MAX * F_HID];
__device__ float g_bufB[N_MAX * F_HID];

__device__ __forceinline__ const float* pick_src(int sel, const float* ext) {
    if (sel == 1) return g_bufA;
    if (sel == 2) return g_bufB;
    return ext;
}
__device__ __forceinline__ float* pick_dst(int sel, float* ext) {
    if (sel == 1) return g_bufA;
    if (sel == 2) return g_bufB;
    return ext;
}

__device__ __forceinline__ uint32_t f2tf32(float f) {
    uint32_t u;
    asm("cvt.rna.tf32.f32 %0, %1;" : "=r"(u) : "f"(f));
    return u;
}

__device__ __forceinline__ void mma_tf32(float* c, const uint32_t* a,
                                         uint32_t b0, uint32_t b1) {
    asm volatile(
        "mma.sync.aligned.m16n8k8.row.col.f32.tf32.tf32.f32 "
        "{%0,%1,%2,%3}, {%4,%5,%6,%7}, {%8,%9}, {%0,%1,%2,%3};"
        : "+f"(c[0]), "+f"(c[1]), "+f"(c[2]), "+f"(c[3])
        : "r"(a[0]), "r"(a[1]), "r"(a[2]), "r"(a[3]), "r"(b0), "r"(b1));
}

// ---------------- detect + init degree (fused) -----------------------------

__global__ void init_detect_kernel(const int* __restrict__ ew, int n) {
    int i = blockIdx.x * blockDim.x + threadIdx.x;
    if (i < n) g_deg[i] = 1;  // self loop
    if (blockIdx.x == 0 && threadIdx.x == 0) {
        int is64 = 1;
        for (int j = 0; j < 32; ++j)
            if (ew[2 * j + 1] != 0) { is64 = 0; break; }
        g_is64 = is64;
    }
}

// ---------------- degree histogram (returns rank) --------------------------

__global__ void deg_hist_kernel(const int* __restrict__ ew, int E) {
    int i = blockIdx.x * blockDim.x + threadIdx.x;
    if (i < E) {
        int d = g_is64 ? ew[2 * E + 2 * i] : ew[E + i];
        g_rank[i] = atomicAdd(&g_deg[d], 1);   // old value = rank (>=1)
    }
}

// ---------------- scan (CSR offsets) ---------------------------------------

__global__ void scan_block_kernel(int n) {
    __shared__ int wsum[32];
    int t = threadIdx.x, lane = t & 31, wid = t >> 5;
    int gid = blockIdx.x * 1024 + t;
    int v = (gid < n) ? (g_deg[gid] - 1) : 0;  // counts exclude self loop
    int s = v;
#pragma unroll
    for (int off = 1; off < 32; off <<= 1) {
        int u = __shfl_up_sync(0xffffffffu, s, off);
        if (lane >= off) s += u;
    }
    if (lane == 31) wsum[wid] = s;
    __syncthreads();
    if (wid == 0) {
        int wv = wsum[lane];
        int ss = wv;
#pragma unroll
        for (int off = 1; off < 32; off <<= 1) {
            int u = __shfl_up_sync(0xffffffffu, ss, off);
            if (lane >= off) ss += u;
        }
        wsum[lane] = ss - wv;                  // exclusive warp offsets
        if (lane == 31) g_blocksums[blockIdx.x] = ss;  // block totals
    }
    __syncthreads();
    if (gid < n) g_rowstart[gid] = s - v + wsum[wid];  // exclusive in block
}

// fold the block-sums scan in (each block rescans 128 sums); also dinv
__global__ void scan_fix_kernel(int n, int E, int nb) {
    __shared__ int pref[128];
    int t = threadIdx.x;
    if (t < 128) pref[t] = (t < nb) ? g_blocksums[t] : 0;
    __syncthreads();
#pragma unroll
    for (int off = 1; off < 128; off <<= 1) {
        int add = (t < 128 && t >= off) ? pref[t - off] : 0;
        __syncthreads();
        if (t < 128) pref[t] += add;
        __syncthreads();
    }
    int gid = blockIdx.x * 256 + t;
    if (gid < n) {
        int b = gid >> 10;
        int base = (b == 0) ? 0 : pref[b - 1];
        g_rowstart[gid] += base;
        g_dinv[gid] = rsqrtf((float)g_deg[gid]);
    }
    if (gid == 0) g_rowstart[n] = E;
}

// atomic-free scatter using saved rank
__global__ void scatter_kernel(const int* __restrict__ ew, int E) {
    int i = blockIdx.x * blockDim.x + threadIdx.x;
    if (i < E) {
        int d, s;
        if (g_is64) {
            s = ew[2 * i];
            d = ew[2 * E + 2 * i];
        } else {
            s = ew[i];
            d = ew[E + i];
        }
        g_colsrc[g_rowstart[d] + g_rank[i] - 1] = s;
    }
}

// ------------------------------ TF32 MMA GEMM ------------------------------
// C[M,NOUT] = A[M,K] @ W[K,NOUT]; optional row-scale by dinv (DINV) or +bias.
// 256 thr = 8 warps in 4x2; warp tile 32 x (NOUT/2); m16n8k8 fragments.

template <int K, int NOUT, bool DINV, bool BIAS>
__global__ __launch_bounds__(256) void mma_gemm_kernel(
    const float* __restrict__ Aext, int asel,
    const float* __restrict__ W, const float* __restrict__ bias,
    float* __restrict__ Cext, int csel, int M) {
    const float* A = pick_src(asel, Aext);
    float*       C = pick_dst(csel, Cext);

    constexpr int KC = 32;
    constexpr int AS = KC + 4;           // bank = (4g+tig)%32 : distinct
    constexpr int WS = NOUT + 8;         // bank = (8tig+g)%32 : distinct
    constexpr int WARP_N = NOUT / 2;     // 32 or 16
    constexpr int NF = WARP_N / 8;       // 4 or 2
    __shared__ float xs[128][AS];        // tf32 bits
    __shared__ float ws[KC][WS];         // tf32 bits

    int t    = threadIdx.x;
    int wid  = t >> 5, lane = t & 31;
    int wm   = wid >> 1;                 // 0..3 -> rows wm*32
    int wn   = wid & 1;                  // cols wn*WARP_N
    int g    = lane >> 2, tig = lane & 3;
    int row0 = blockIdx.x * 128;

    float c[2][NF][4];
#pragma unroll
    for (int mf = 0; mf < 2; ++mf)
#pragma unroll
        for (int nf = 0; nf < NF; ++nf)
#pragma unroll
            for (int j = 0; j < 4; ++j) c[mf][nf][j] = 0.f;

    for (int kc = 0; kc < K; kc += KC) {
#pragma unroll
        for (int i = 0; i < 4; ++i) {
            int f4 = t + i * 256;
            int r  = f4 >> 3;
            int k4 = (f4 & 7) * 4;
            float4 v = make_float4(0.f, 0.f, 0.f, 0.f);
            int gr = row0 + r;
            if (gr < M) v = *(const float4*)&A[(size_t)gr * K + kc + k4];
            float4 tv;
            tv.x = __uint_as_float(f2tf32(v.x));
            tv.y = __uint_as_float(f2tf32(v.y));
            tv.z = __uint_as_float(f2tf32(v.z));
            tv.w = __uint_as_float(f2tf32(v.w));
            *(float4*)&xs[r][k4] = tv;
        }
#pragma unroll
        for (int i = 0; i < (KC * NOUT) / 1024; ++i) {
            int f4 = t + i * 256;
            int k  = f4 / (NOUT / 4);
            int c4 = (f4 % (NOUT / 4)) * 4;
            float4 v = *(const float4*)&W[(kc + k) * NOUT + c4];
            float4 tv;
            tv.x = __uint_as_float(f2tf32(v.x));
            tv.y = __uint_as_float(f2tf32(v.y));
            tv.z = __uint_as_float(f2tf32(v.z));
            tv.w = __uint_as_float(f2tf32(v.w));
            *(float4*)&ws[k][c4] = tv;
        }
        __syncthreads();
#pragma unroll
        for (int ks = 0; ks < KC / 8; ++ks) {
            int k0 = ks * 8;
            uint32_t a[2][4];
#pragma unroll
            for (int mf = 0; mf < 2; ++mf) {
                int rb = wm * 32 + mf * 16 + g;
                a[mf][0] = __float_as_uint(xs[rb][k0 + tig]);
                a[mf][1] = __float_as_uint(xs[rb + 8][k0 + tig]);
                a[mf][2] = __float_as_uint(xs[rb][k0 + tig + 4]);
                a[mf][3] = __float_as_uint(xs[rb + 8][k0 + tig + 4]);
            }
#pragma unroll
            for (int nf = 0; nf < NF; ++nf) {
                int nb = wn * WARP_N + nf * 8 + g;
                uint32_t b0 = __float_as_uint(ws[k0 + tig][nb]);
                uint32_t b1 = __float_as_uint(ws[k0 + tig + 4][nb]);
                mma_tf32(c[0][nf], a[0], b0, b1);
                mma_tf32(c[1][nf], a[1], b0, b1);
            }
        }
        __syncthreads();
    }

#pragma unroll
    for (int mf = 0; mf < 2; ++mf) {
        int rA = row0 + wm * 32 + mf * 16 + g;
        int rB = rA + 8;
        float sA = 1.f, sB = 1.f;
        if (DINV) {
            if (rA < M) sA = g_dinv[rA];
            if (rB < M) sB = g_dinv[rB];
        }
#pragma unroll
        for (int nf = 0; nf < NF; ++nf) {
            int cb = wn * WARP_N + nf * 8 + tig * 2;
            float b0 = 0.f, b1 = 0.f;
            if (BIAS) { b0 = bias[cb]; b1 = bias[cb + 1]; }
            if (rA < M)
                *(float2*)&C[(size_t)rA * NOUT + cb] =
                    make_float2(c[mf][nf][0] * sA + b0, c[mf][nf][1] * sA + b1);
            if (rB < M)
                *(float2*)&C[(size_t)rB * NOUT + cb] =
                    make_float2(c[mf][nf][2] * sB + b0, c[mf][nf][3] * sB + b1);
        }
    }
}

// ------------------------------ aggregation --------------------------------
// hs dinv-scaled fp32. One warp per dst node; 8-deep gather pipeline.
// out[d] = relu( (hs[d] + sum_e hs[src_e]) * dinv[d] + b )

__global__ __launch_bounds__(256) void aggregate_kernel(
    int hsel, const float* __restrict__ bias, int osel, int n) {
    const float2* h   = (const float2*)pick_src(hsel, nullptr);
    float2*       out = (float2*)pick_dst(osel, nullptr);

    int gw   = (blockIdx.x * blockDim.x + threadIdx.x) >> 5;
    int lane = threadIdx.x & 31;
    if (gw >= n) return;
    int d = gw;
    float di = g_dinv[d];
    float2 hv = h[(size_t)d * 32 + lane];
    float ax = hv.x, ay = hv.y;          // self term (hs[d])

    int e0 = g_rowstart[d], e1 = g_rowstart[d + 1];
    int e  = e0;
    // 8-deep pipeline: 8 independent index loads then 8 independent gathers
    for (; e + 8 <= e1; e += 8) {
        int s0 = g_colsrc[e + 0];
        int s1 = g_colsrc[e + 1];
        int s2 = g_colsrc[e + 2];
        int s3 = g_colsrc[e + 3];
        int s4 = g_colsrc[e + 4];
        int s5 = g_colsrc[e + 5];
        int s6 = g_colsrc[e + 6];
        int s7 = g_colsrc[e + 7];
        float2 v0 = h[(size_t)s0 * 32 + lane];
        float2 v1 = h[(size_t)s1 * 32 + lane];
        float2 v2 = h[(size_t)s2 * 32 + lane];
        float2 v3 = h[(size_t)s3 * 32 + lane];
        float2 v4 = h[(size_t)s4 * 32 + lane];
        float2 v5 = h[(size_t)s5 * 32 + lane];
        float2 v6 = h[(size_t)s6 * 32 + lane];
        float2 v7 = h[(size_t)s7 * 32 + lane];
        ax += v0.x; ay += v0.y;
        ax += v1.x; ay += v1.y;
        ax += v2.x; ay += v2.y;
        ax += v3.x; ay += v3.y;
        ax += v4.x; ay += v4.y;
        ax += v5.x; ay += v5.y;
        ax += v6.x; ay += v6.y;
        ax += v7.x; ay += v7.y;
    }
    for (; e + 4 <= e1; e += 4) {
        int s0 = g_colsrc[e + 0];
        int s1 = g_colsrc[e + 1];
        int s2 = g_colsrc[e + 2];
        int s3 = g_colsrc[e + 3];
        float2 v0 = h[(size_t)s0 * 32 + lane];
        float2 v1 = h[(size_t)s1 * 32 + lane];
        float2 v2 = h[(size_t)s2 * 32 + lane];
        float2 v3 = h[(size_t)s3 * 32 + lane];
        ax += v0.x; ay += v0.y;
        ax += v1.x; ay += v1.y;
        ax += v2.x; ay += v2.y;
        ax += v3.x; ay += v3.y;
    }
    for (; e < e1; ++e) {
        int s = g_colsrc[e];
        float2 v = h[(size_t)s * 32 + lane];
        ax += v.x; ay += v.y;
    }

    ax = fmaf(ax, di, bias[2 * lane]);
    ay = fmaf(ay, di, bias[2 * lane + 1]);
    ax = fmaxf(ax, 0.f);
    ay = fmaxf(ay, 0.f);
    out[(size_t)d * 32 + lane] = make_float2(ax, ay);
}

// ------------------------------ launch -------------------------------------

extern "C" void kernel_launch(void* const* d_in, const int* in_sizes, int n_in,
                              void* d_out, int out_size) {
    const float* x   = (const float*)d_in[0];
    const int*   ew  = (const int*)d_in[1];    // edge words (int32 view)
    const float* W1  = (const float*)d_in[3];
    const float* b1  = (const float*)d_in[4];
    const float* W2  = (const float*)d_in[5];
    const float* b2  = (const float*)d_in[6];
    const float* Wfc = (const float*)d_in[7];
    const float* bfc = (const float*)d_in[8];
    float*       out = (float*)d_out;

    int n = in_sizes[0] / F_IN;
    int E = in_sizes[1] / 2;

    int nb  = (n + 1023) / 1024;
    int gbN = (n + 255) / 256;
    int gbE = (E + 255) / 256;

    init_detect_kernel<<<gbN, 256>>>(ew, n);
    deg_hist_kernel<<<gbE, 256>>>(ew, E);
    scan_block_kernel<<<nb, 1024>>>(n);
    scan_fix_kernel<<<gbN, 256>>>(n, E, nb);
    scatter_kernel<<<gbE, 256>>>(ew, E);

    int gbG  = (n + 127) / 128;
    int gbAg = (n * 32 + 255) / 256;

    // layer 1: bufA = (x@W1)*dinv ; bufB = relu(agg*dinv + b1)
    mma_gemm_kernel<F_IN, F_HID, true, false><<<gbG, 256>>>(
        x, 0, W1, nullptr, nullptr, 1, n);
    aggregate_kernel<<<gbAg, 256>>>(1, b1, 2, n);
    // layer 2
    mma_gemm_kernel<F_HID, F_HID, true, false><<<gbG, 256>>>(
        nullptr, 2, W2, nullptr, nullptr, 1, n);
    aggregate_kernel<<<gbAg, 256>>>(1, b2, 2, n);
    // FC: out = bufB@Wfc + bfc
    mma_gemm_kernel<F_HID, F_OUT, false, true><<<gbG, 256>>>(
        nullptr, 2, Wfc, bfc, out, 0, n);
}

// round 16
// speedup vs baseline: 1.0551x; 1.0027x over previous
#include <cuda_runtime.h>
#include <cuda_fp16.h>
#include <cstdint>

// ---------------------------------------------------------------------------
// GCN via TF32 tensor-core GEMMs + CSR warp aggregation.
//   hs = (x@W) * dinv[row]
//   out[d] = relu( (hs[d] + sum_{e->d} hs[src]) * dinv[d] + b )
// Aggregate: one warp per node; two half-warps (16 lanes x float4) process
// even/odd edges concurrently, 4-deep pipeline each -> 8 edge-rows in flight.
// ---------------------------------------------------------------------------

#define N_MAX 100000
#define E_MAX 1600000
#define F_IN  128
#define F_HID 64
#define F_OUT 32

__device__ int   g_is64;
__device__ int   g_deg[N_MAX];
__device__ float g_dinv[N_MAX];
__device__ int   g_rowstart[N_MAX + 1];
__device__ int   g_rank[E_MAX];
__device__ int   g_colsrc[E_MAX];
__device__ int   g_blocksums[128];
__device__ float g_bufA[N_MAX * F_HID];
__device__ float g_bufB[N_MAX * F_HID];

__device__ __forceinline__ const float* pick_src(int sel, const float* ext) {
    if (sel == 1) return g_bufA;
    if (sel == 2) return g_bufB;
    return ext;
}
__device__ __forceinline__ float* pick_dst(int sel, float* ext) {
    if (sel == 1) return g_bufA;
    if (sel == 2) return g_bufB;
    return ext;
}

__device__ __forceinline__ uint32_t f2tf32(float f) {
    uint32_t u;
    asm("cvt.rna.tf32.f32 %0, %1;" : "=r"(u) : "f"(f));
    return u;
}

__device__ __forceinline__ void mma_tf32(float* c, const uint32_t* a,
                                         uint32_t b0, uint32_t b1) {
    asm volatile(
        "mma.sync.aligned.m16n8k8.row.col.f32.tf32.tf32.f32 "
        "{%0,%1,%2,%3}, {%4,%5,%6,%7}, {%8,%9}, {%0,%1,%2,%3};"
        : "+f"(c[0]), "+f"(c[1]), "+f"(c[2]), "+f"(c[3])
        : "r"(a[0]), "r"(a[1]), "r"(a[2]), "r"(a[3]), "r"(b0), "r"(b1));
}

// ---------------- detect + init degree (fused) -----------------------------

__global__ void init_detect_kernel(const int* __restrict__ ew, int n) {
    int i = blockIdx.x * blockDim.x + threadIdx.x;
    if (i < n) g_deg[i] = 1;  // self loop
    if (blockIdx.x == 0 && threadIdx.x == 0) {
        int is64 = 1;
        for (int j = 0; j < 32; ++j)
            if (ew[2 * j + 1] != 0) { is64 = 0; break; }
        g_is64 = is64;
    }
}

// ---------------- degree histogram (returns rank) --------------------------

__global__ void deg_hist_kernel(const int* __restrict__ ew, int E) {
    int i = blockIdx.x * blockDim.x + threadIdx.x;
    if (i < E) {
        int d = g_is64 ? ew[2 * E + 2 * i] : ew[E + i];
        g_rank[i] = atomicAdd(&g_deg[d], 1);   // old value = rank (>=1)
    }
}

// ---------------- scan (CSR offsets) ---------------------------------------

__global__ void scan_block_kernel(int n) {
    __shared__ int wsum[32];
    int t = threadIdx.x, lane = t & 31, wid = t >> 5;
    int gid = blockIdx.x * 1024 + t;
    int v = (gid < n) ? (g_deg[gid] - 1) : 0;  // counts exclude self loop
    int s = v;
#pragma unroll
    for (int off = 1; off < 32; off <<= 1) {
        int u = __shfl_up_sync(0xffffffffu, s, off);
        if (lane >= off) s += u;
    }
    if (lane == 31) wsum[wid] = s;
    __syncthreads();
    if (wid == 0) {
        int wv = wsum[lane];
        int ss = wv;
#pragma unroll
        for (int off = 1; off < 32; off <<= 1) {
            int u = __shfl_up_sync(0xffffffffu, ss, off);
            if (lane >= off) ss += u;
        }
        wsum[lane] = ss - wv;                  // exclusive warp offsets
        if (lane == 31) g_blocksums[blockIdx.x] = ss;  // block totals
    }
    __syncthreads();
    if (gid < n) g_rowstart[gid] = s - v + wsum[wid];  // exclusive in block
}

// fold the block-sums scan in (each block rescans 128 sums); also dinv
__global__ void scan_fix_kernel(int n, int E, int nb) {
    __shared__ int pref[128];
    int t = threadIdx.x;
    if (t < 128) pref[t] = (t < nb) ? g_blocksums[t] : 0;
    __syncthreads();
#pragma unroll
    for (int off = 1; off < 128; off <<= 1) {
        int add = (t < 128 && t >= off) ? pref[t - off] : 0;
        __syncthreads();
        if (t < 128) pref[t] += add;
        __syncthreads();
    }
    int gid = blockIdx.x * 256 + t;
    if (gid < n) {
        int b = gid >> 10;
        int base = (b == 0) ? 0 : pref[b - 1];
        g_rowstart[gid] += base;
        g_dinv[gid] = rsqrtf((float)g_deg[gid]);
    }
    if (gid == 0) g_rowstart[n] = E;
}

// atomic-free scatter using saved rank
__global__ void scatter_kernel(const int* __restrict__ ew, int E) {
    int i = blockIdx.x * blockDim.x + threadIdx.x;
    if (i < E) {
        int d, s;
        if (g_is64) {
            s = ew[2 * i];
            d = ew[2 * E + 2 * i];
        } else {
            s = ew[i];
            d = ew[E + i];
        }
        g_colsrc[g_rowstart[d] + g_rank[i] - 1] = s;
    }
}

// ------------------------------ TF32 MMA GEMM ------------------------------

template <int K, int NOUT, bool DINV, bool BIAS>
__global__ __launch_bounds__(256) void mma_gemm_kernel(
    const float* __restrict__ Aext, int asel,
    const float* __restrict__ W, const float* __restrict__ bias,
    float* __restrict__ Cext, int csel, int M) {
    const float* A = pick_src(asel, Aext);
    float*       C = pick_dst(csel, Cext);

    constexpr int KC = 32;
    constexpr int AS = KC + 4;           // bank = (4g+tig)%32 : distinct
    constexpr int WS = NOUT + 8;         // bank = (8tig+g)%32 : distinct
    constexpr int WARP_N = NOUT / 2;     // 32 or 16
    constexpr int NF = WARP_N / 8;       // 4 or 2
    __shared__ float xs[128][AS];        // tf32 bits
    __shared__ float ws[KC][WS];         // tf32 bits

    int t    = threadIdx.x;
    int wid  = t >> 5, lane = t & 31;
    int wm   = wid >> 1;                 // 0..3 -> rows wm*32
    int wn   = wid & 1;                  // cols wn*WARP_N
    int g    = lane >> 2, tig = lane & 3;
    int row0 = blockIdx.x * 128;

    float c[2][NF][4];
#pragma unroll
    for (int mf = 0; mf < 2; ++mf)
#pragma unroll
        for (int nf = 0; nf < NF; ++nf)
#pragma unroll
            for (int j = 0; j < 4; ++j) c[mf][nf][j] = 0.f;

    for (int kc = 0; kc < K; kc += KC) {
#pragma unroll
        for (int i = 0; i < 4; ++i) {
            int f4 = t + i * 256;
            int r  = f4 >> 3;
            int k4 = (f4 & 7) * 4;
            float4 v = make_float4(0.f, 0.f, 0.f, 0.f);
            int gr = row0 + r;
            if (gr < M) v = *(const float4*)&A[(size_t)gr * K + kc + k4];
            float4 tv;
            tv.x = __uint_as_float(f2tf32(v.x));
            tv.y = __uint_as_float(f2tf32(v.y));
            tv.z = __uint_as_float(f2tf32(v.z));
            tv.w = __uint_as_float(f2tf32(v.w));
            *(float4*)&xs[r][k4] = tv;
        }
#pragma unroll
        for (int i = 0; i < (KC * NOUT) / 1024; ++i) {
            int f4 = t + i * 256;
            int k  = f4 / (NOUT / 4);
            int c4 = (f4 % (NOUT / 4)) * 4;
            float4 v = *(const float4*)&W[(kc + k) * NOUT + c4];
            float4 tv;
            tv.x = __uint_as_float(f2tf32(v.x));
            tv.y = __uint_as_float(f2tf32(v.y));
            tv.z = __uint_as_float(f2tf32(v.z));
            tv.w = __uint_as_float(f2tf32(v.w));
            *(float4*)&ws[k][c4] = tv;
        }
        __syncthreads();
#pragma unroll
        for (int ks = 0; ks < KC / 8; ++ks) {
            int k0 = ks * 8;
            uint32_t a[2][4];
#pragma unroll
            for (int mf = 0; mf < 2; ++mf) {
                int rb = wm * 32 + mf * 16 + g;
                a[mf][0] = __float_as_uint(xs[rb][k0 + tig]);
                a[mf][1] = __float_as_uint(xs[rb + 8][k0 + tig]);
                a[mf][2] = __float_as_uint(xs[rb][k0 + tig + 4]);
                a[mf][3] = __float_as_uint(xs[rb + 8][k0 + tig + 4]);
            }
#pragma unroll
            for (int nf = 0; nf < NF; ++nf) {
                int nb = wn * WARP_N + nf * 8 + g;
                uint32_t b0 = __float_as_uint(ws[k0 + tig][nb]);
                uint32_t b1 = __float_as_uint(ws[k0 + tig + 4][nb]);
                mma_tf32(c[0][nf], a[0], b0, b1);
                mma_tf32(c[1][nf], a[1], b0, b1);
            }
        }
        __syncthreads();
    }

#pragma unroll
    for (int mf = 0; mf < 2; ++mf) {
        int rA = row0 + wm * 32 + mf * 16 + g;
        int rB = rA + 8;
        float sA = 1.f, sB = 1.f;
        if (DINV) {
            if (rA < M) sA = g_dinv[rA];
            if (rB < M) sB = g_dinv[rB];
        }
#pragma unroll
        for (int nf = 0; nf < NF; ++nf) {
            int cb = wn * WARP_N + nf * 8 + tig * 2;
            float b0 = 0.f, b1 = 0.f;
            if (BIAS) { b0 = bias[cb]; b1 = bias[cb + 1]; }
            if (rA < M)
                *(float2*)&C[(size_t)rA * NOUT + cb] =
                    make_float2(c[mf][nf][0] * sA + b0, c[mf][nf][1] * sA + b1);
            if (rB < M)
                *(float2*)&C[(size_t)rB * NOUT + cb] =
                    make_float2(c[mf][nf][2] * sB + b0, c[mf][nf][3] * sB + b1);
        }
    }
}

// ------------------------------ aggregation --------------------------------
// One warp per node. Half-warps process even/odd edges: 16 lanes x float4
// cover the 64-float row. 4-deep pipeline per half -> 8 edge-rows in flight.
// Cross-half combine via shfl_xor(16); epilogue on half 0.

__global__ __launch_bounds__(256) void aggregate_kernel(
    int hsel, const float* __restrict__ bias, int osel, int n) {
    const float4* h   = (const float4*)pick_src(hsel, nullptr);
    float4*       out = (float4*)pick_dst(osel, nullptr);

    int gw   = (blockIdx.x * blockDim.x + threadIdx.x) >> 5;
    int lane = threadIdx.x & 31;
    if (gw >= n) return;
    int d    = gw;
    int half = lane >> 4;
    int li   = lane & 15;

    float ax = 0.f, ay = 0.f, az = 0.f, aw = 0.f;
    if (half == 0) {                      // self term on half 0 only
        float4 hv = h[(size_t)d * 16 + li];
        ax = hv.x; ay = hv.y; az = hv.z; aw = hv.w;
    }

    int e0 = g_rowstart[d], e1 = g_rowstart[d + 1];
    int e  = e0 + half;                   // this half's edges: stride 2
    // 4-deep pipeline per half (8 edge-rows in flight per warp)
    for (; e + 6 < e1; e += 8) {
        int s0 = g_colsrc[e + 0];
        int s1 = g_colsrc[e + 2];
        int s2 = g_colsrc[e + 4];
        int s3 = g_colsrc[e + 6];
        float4 v0 = h[(size_t)s0 * 16 + li];
        float4 v1 = h[(size_t)s1 * 16 + li];
        float4 v2 = h[(size_t)s2 * 16 + li];
        float4 v3 = h[(size_t)s3 * 16 + li];
        ax += v0.x; ay += v0.y; az += v0.z; aw += v0.w;
        ax += v1.x; ay += v1.y; az += v1.z; aw += v1.w;
        ax += v2.x; ay += v2.y; az += v2.z; aw += v2.w;
        ax += v3.x; ay += v3.y; az += v3.z; aw += v3.w;
    }
    for (; e < e1; e += 2) {
        int s = g_colsrc[e];
        float4 v = h[(size_t)s * 16 + li];
        ax += v.x; ay += v.y; az += v.z; aw += v.w;
    }

    // combine halves (lane i gets lane i^16's partial)
    ax += __shfl_xor_sync(0xffffffffu, ax, 16);
    ay += __shfl_xor_sync(0xffffffffu, ay, 16);
    az += __shfl_xor_sync(0xffffffffu, az, 16);
    aw += __shfl_xor_sync(0xffffffffu, aw, 16);

    if (half == 0) {
        float di = g_dinv[d];
        float4 b = *(const float4*)&bias[4 * li];
        float4 r;
        r.x = fmaxf(fmaf(ax, di, b.x), 0.f);
        r.y = fmaxf(fmaf(ay, di, b.y), 0.f);
        r.z = fmaxf(fmaf(az, di, b.z), 0.f);
        r.w = fmaxf(fmaf(aw, di, b.w), 0.f);
        out[(size_t)d * 16 + li] = r;
    }
}

// ------------------------------ launch -------------------------------------

extern "C" void kernel_launch(void* const* d_in, const int* in_sizes, int n_in,
                              void* d_out, int out_size) {
    const float* x   = (const float*)d_in[0];
    const int*   ew  = (const int*)d_in[1];    // edge words (int32 view)
    const float* W1  = (const float*)d_in[3];
    const float* b1  = (const float*)d_in[4];
    const float* W2  = (const float*)d_in[5];
    const float* b2  = (const float*)d_in[6];
    const float* Wfc = (const float*)d_in[7];
    const float* bfc = (const float*)d_in[8];
    float*       out = (float*)d_out;

    int n = in_sizes[0] / F_IN;
    int E = in_sizes[1] / 2;

    int nb  = (n + 1023) / 1024;
    int gbN = (n + 255) / 256;
    int gbE = (E + 255) / 256;

    init_detect_kernel<<<gbN, 256>>>(ew, n);
    deg_hist_kernel<<<gbE, 256>>>(ew, E);
    scan_block_kernel<<<nb, 1024>>>(n);
    scan_fix_kernel<<<gbN, 256>>>(n, E, nb);
    scatter_kernel<<<gbE, 256>>>(ew, E);

    int gbG  = (n + 127) / 128;
    int gbAg = (n * 32 + 255) / 256;

    // layer 1: bufA = (x@W1)*dinv ; bufB = relu(agg*dinv + b1)
    mma_gemm_kernel<F_IN, F_HID, true, false><<<gbG, 256>>>(
        x, 0, W1, nullptr, nullptr, 1, n);
    aggregate_kernel<<<gbAg, 256>>>(1, b1, 2, n);
    // layer 2
    mma_gemm_kernel<F_HID, F_HID, true, false><<<gbG, 256>>>(
        nullptr, 2, W2, nullptr, nullptr, 1, n);
    aggregate_kernel<<<gbAg, 256>>>(1, b2, 2, n);
    // FC: out = bufB@Wfc + bfc
    mma_gemm_kernel<F_HID, F_OUT, false, true><<<gbG, 256>>>(
        nullptr, 2, Wfc, bfc, out, 0, n);
}